// round 2
// baseline (speedup 1.0000x reference)
#include <cuda_runtime.h>

// Slice_windows: (32,1,1024,1024) f32 -> (32,8) f32
// For k = 2,4,...,256: non-overlapping kxk window sums, Shannon entropy of
// p1 = s/k^2, mean over windows per batch.
//
// Design: one CTA per 256x256 tile (512 CTAs). Each CTA reads its tile from
// HBM once, builds the 2x2 sum-pyramid in smem (levels k=2..256 all contained
// in the tile), accumulates per-level entropy, writes 8 partials to a global
// scratch. A finalize kernel (1 block) reduces 16 tiles per (b,level)
// deterministically and normalizes by window count.

#define NLEVELS 8
#define TILES_PER_IMG 16
#define NBATCH 32
#define NBLOCKS (NBATCH * TILES_PER_IMG)
#define NTHREADS 512

// pyramid float offsets: lvl sizes 128^2,64^2,...,1  -> total 21845 floats
#define SMEM_FLOATS 21845
#define SMEM_BYTES (SMEM_FLOATS * 4)

__device__ float g_partials[NBLOCKS * NLEVELS];

__device__ __forceinline__ float plogp(float p) {
    // p * log2(p), 0 at p == 0
    return (p > 0.f) ? p * __log2f(p) : 0.f;
}

__global__ void __launch_bounds__(NTHREADS, 2)
slice_windows_main(const float* __restrict__ x)
{
    extern __shared__ float sm[];

    const int tid  = threadIdx.x;
    const int bid  = blockIdx.x;
    const int b    = bid >> 4;
    const int tile = bid & 15;
    const int row0 = (tile >> 2) * 256;
    const int col0 = (tile & 3) * 256;
    const float* __restrict__ img = x + (size_t)b * 1024 * 1024;

    float eacc[NLEVELS];
#pragma unroll
    for (int l = 0; l < NLEVELS; l++) eacc[l] = 0.f;

    // ---- Level 0 (k=2): read gmem tile, write 128x128 sums to sm[0..16383]
    {
        const float inv_n = 0.25f;
        const int r  = tid >> 6;   // 0..7 : output row within iteration group
        const int c4 = tid & 63;   // each thread: 2 outputs via float4 per row
#pragma unroll 4
        for (int it = 0; it < 16; ++it) {
            const int orow = it * 8 + r;            // 0..127
            const int grow = row0 + orow * 2;
            const float4 a0 = *((const float4*)(img + (size_t)grow * 1024 + col0) + c4);
            const float4 a1 = *((const float4*)(img + (size_t)(grow + 1) * 1024 + col0) + c4);
            const float s0 = (a0.x + a0.y) + (a1.x + a1.y);
            const float s1 = (a0.z + a0.w) + (a1.z + a1.w);
            const float p0 = s0 * inv_n;
            const float p1 = s1 * inv_n;
            eacc[0] -= plogp(p0) + plogp(1.f - p0);
            eacc[0] -= plogp(p1) + plogp(1.f - p1);
            sm[orow * 128 + c4 * 2]     = s0;
            sm[orow * 128 + c4 * 2 + 1] = s1;
        }
    }
    __syncthreads();

    // ---- Levels 1..7: pyramid reduction in smem
    int in_off = 0, in_dim = 128, out_off = 16384;
#pragma unroll
    for (int l = 1; l < NLEVELS; l++) {
        const int out_dim = in_dim >> 1;
        const int nout = out_dim * out_dim;
        const float inv_n = 1.0f / (float)(1 << (2 * (l + 1)));  // 1/k^2, k=2^(l+1)
        for (int i = tid; i < nout; i += NTHREADS) {
            const int oy = i / out_dim;
            const int ox = i - oy * out_dim;
            const float* rp0 = sm + in_off + (2 * oy) * in_dim + 2 * ox;
            const float* rp1 = rp0 + in_dim;
            const float s = (rp0[0] + rp0[1]) + (rp1[0] + rp1[1]);
            const float p = s * inv_n;
            eacc[l] -= plogp(p) + plogp(1.f - p);
            sm[out_off + i] = s;
        }
        __syncthreads();
        in_off = out_off;
        in_dim = out_dim;
        out_off += nout;
    }
    // after final sync, level-0 smem region is dead -> reuse for reduction

    // ---- Block-reduce the 8 per-thread entropy accumulators
    const int lane = tid & 31;
    const int warp = tid >> 5;   // 16 warps
#pragma unroll
    for (int l = 0; l < NLEVELS; l++) {
        float v = eacc[l];
#pragma unroll
        for (int o = 16; o > 0; o >>= 1)
            v += __shfl_down_sync(0xffffffffu, v, o);
        if (lane == 0) sm[warp * NLEVELS + l] = v;
    }
    __syncthreads();
    if (tid < NLEVELS) {
        float s = 0.f;
#pragma unroll
        for (int w = 0; w < 16; w++) s += sm[w * NLEVELS + tid];
        g_partials[bid * NLEVELS + tid] = s;
    }
}

__global__ void slice_windows_finalize(float* __restrict__ out)
{
    const int idx = threadIdx.x;           // 0..255 => (b,l)
    if (idx < NBATCH * NLEVELS) {
        const int b = idx >> 3;
        const int l = idx & 7;
        float s = 0.f;
#pragma unroll
        for (int t = 0; t < TILES_PER_IMG; t++)
            s += g_partials[(b * TILES_PER_IMG + t) * NLEVELS + l];
        const int d = 1024 >> (l + 1);     // windows per side, k = 2^(l+1)
        out[idx] = s / (float)(d * d);
    }
}

extern "C" void kernel_launch(void* const* d_in, const int* in_sizes, int n_in,
                              void* d_out, int out_size)
{
    (void)in_sizes; (void)n_in; (void)out_size;
    const float* x = (const float*)d_in[0];
    float* out = (float*)d_out;

    cudaFuncSetAttribute(slice_windows_main,
                         cudaFuncAttributeMaxDynamicSharedMemorySize, SMEM_BYTES);
    slice_windows_main<<<NBLOCKS, NTHREADS, SMEM_BYTES>>>(x);
    slice_windows_finalize<<<1, 256>>>(out);
}

// round 3
// speedup vs baseline: 1.0609x; 1.0609x over previous
#include <cuda_runtime.h>

// Slice_windows: (32,1,1024,1024) f32 -> (32,8) f32
// For k = 2,4,...,256: non-overlapping kxk window sums, Shannon entropy of
// p1 = s/k^2, mean over windows per batch.
//
// R3 design:
//  - One CTA per 256x256 tile (512 CTAs, 512 threads).
//  - Gmem pass: each thread handles 4x4 blocks -> computes k=2 entropies (4
//    windows) and the k=4 sum+entropy in registers. Only the 64x64 k=4 sums
//    go to smem -> smem = 21.8 KB -> 4 CTAs/SM -> single wave.
//  - Smem pyramid for k=8..256 (64x64 -> 1x1).
//  - Finalize fused via threadfence-reduction: last-arriving CTA sums the
//    512x8 partials in a fixed order (deterministic) and writes (32,8).

#define NLEVELS 8
#define TILES_PER_IMG 16
#define NBATCH 32
#define NBLOCKS (NBATCH * TILES_PER_IMG)
#define NTHREADS 512

// pyramid: 64^2 + 32^2 + 16^2 + 8^2 + 4^2 + 2^2 + 1 = 5461 floats (21844 B)
#define SMEM_FLOATS 5461

__device__ float g_partials[NBLOCKS * NLEVELS];
__device__ int   g_count = 0;

__device__ __forceinline__ float plogp(float p) {
    // p * log2(p), 0 at p == 0
    return (p > 0.f) ? p * __log2f(p) : 0.f;
}
__device__ __forceinline__ float ent(float s, float inv_n) {
    const float p = s * inv_n;
    return plogp(p) + plogp(1.f - p);
}

__global__ void __launch_bounds__(NTHREADS, 4)
slice_windows_fused(const float* __restrict__ x, float* __restrict__ out)
{
    __shared__ float sm[SMEM_FLOATS];
    __shared__ bool  is_last;

    const int tid  = threadIdx.x;
    const int bid  = blockIdx.x;
    const int b    = bid >> 4;
    const int tile = bid & 15;
    const int row0 = (tile >> 2) * 256;
    const int col0 = (tile & 3) * 256;
    const float* __restrict__ img = x + (size_t)b * 1024 * 1024;

    float eacc[NLEVELS];
#pragma unroll
    for (int l = 0; l < NLEVELS; l++) eacc[l] = 0.f;

    // ---- Gmem pass: k=2 and k=4 in registers; store 64x64 k=4 sums to smem.
    {
        const int c4 = tid & 63;          // 4-col group: 0..63
        const int r  = tid >> 6;          // 0..7
        const float* base = img + (size_t)row0 * 1024 + col0 + c4 * 4;
#pragma unroll
        for (int it = 0; it < 8; ++it) {
            const int orow = it * 8 + r;                // k=4 output row 0..63
            const float* p = base + (size_t)orow * 4096;
            const float4 a0 = *(const float4*)(p);
            const float4 a1 = *(const float4*)(p + 1024);
            const float4 a2 = *(const float4*)(p + 2048);
            const float4 a3 = *(const float4*)(p + 3072);
            const float s00 = (a0.x + a0.y) + (a1.x + a1.y);
            const float s01 = (a0.z + a0.w) + (a1.z + a1.w);
            const float s10 = (a2.x + a2.y) + (a3.x + a3.y);
            const float s11 = (a2.z + a2.w) + (a3.z + a3.w);
            eacc[0] -= ent(s00, 0.25f) + ent(s01, 0.25f)
                     + ent(s10, 0.25f) + ent(s11, 0.25f);
            const float S = (s00 + s01) + (s10 + s11);
            eacc[1] -= ent(S, 0.0625f);
            sm[orow * 64 + c4] = S;
        }
    }
    __syncthreads();

    // ---- Pyramid in smem: levels l=2..7 (k=8..256), 64x64 -> 1x1.
    int in_off = 0, in_dim = 64, out_off = 4096;
#pragma unroll
    for (int l = 2; l < NLEVELS; l++) {
        const int out_dim = in_dim >> 1;
        const int nout = out_dim * out_dim;
        const float inv_n = 1.0f / (float)(1 << (2 * (l + 1)));  // 1/k^2
        for (int i = tid; i < nout; i += NTHREADS) {
            const int oy = i / out_dim;
            const int ox = i - oy * out_dim;
            const float* rp0 = sm + in_off + (2 * oy) * in_dim + 2 * ox;
            const float* rp1 = rp0 + in_dim;
            const float s = (rp0[0] + rp0[1]) + (rp1[0] + rp1[1]);
            eacc[l] -= ent(s, inv_n);
            sm[out_off + i] = s;
        }
        __syncthreads();
        in_off = out_off;
        in_dim = out_dim;
        out_off += nout;
    }
    // Region sm[0..4095] is dead now -> reuse for the block reduction.

    // ---- Block-reduce the 8 per-thread entropy accumulators.
    const int lane = tid & 31;
    const int warp = tid >> 5;   // 16 warps
#pragma unroll
    for (int l = 0; l < NLEVELS; l++) {
        float v = eacc[l];
#pragma unroll
        for (int o = 16; o > 0; o >>= 1)
            v += __shfl_down_sync(0xffffffffu, v, o);
        if (lane == 0) sm[warp * NLEVELS + l] = v;
    }
    __syncthreads();
    if (tid < NLEVELS) {
        float s = 0.f;
#pragma unroll
        for (int w = 0; w < 16; w++) s += sm[w * NLEVELS + tid];
        g_partials[bid * NLEVELS + tid] = s;
    }

    // ---- Fused finalize: last-arriving CTA reduces all partials.
    __threadfence();
    if (tid == 0) {
        const int prev = atomicAdd(&g_count, 1);
        is_last = (prev == NBLOCKS - 1);
    }
    __syncthreads();
    if (is_last) {
        if (tid < NBATCH * NLEVELS) {
            const int bb = tid >> 3;
            const int l  = tid & 7;
            float s = 0.f;
#pragma unroll
            for (int t = 0; t < TILES_PER_IMG; t++)
                s += __ldcg(&g_partials[(bb * TILES_PER_IMG + t) * NLEVELS + l]);
            const int d = 1024 >> (l + 1);   // windows per side, k = 2^(l+1)
            out[bb * NLEVELS + l] = s / (float)(d * d);
        }
        if (tid == 0) g_count = 0;           // reset for graph replay
    }
}

extern "C" void kernel_launch(void* const* d_in, const int* in_sizes, int n_in,
                              void* d_out, int out_size)
{
    (void)in_sizes; (void)n_in; (void)out_size;
    const float* x = (const float*)d_in[0];
    float* out = (float*)d_out;
    slice_windows_fused<<<NBLOCKS, NTHREADS>>>(x, out);
}

// round 4
// speedup vs baseline: 1.0703x; 1.0088x over previous
#include <cuda_runtime.h>

// Slice_windows: (32,1,1024,1024) f32 -> (32,8) f32
// For k = 2,4,...,256: non-overlapping kxk window sums, Shannon entropy of
// p1 = s/k^2, mean over windows per batch.
//
// R4 design:
//  - One CTA per 256x256 tile (512 CTAs), 256 threads, launch_bounds(256,4)
//    -> 64 regs/thread so ptxas can pipeline 8+ LDG.128 in flight (R3 was
//    reg-starved at 32 regs -> DRAM stuck at 62%).
//  - Gmem pass: each thread does 16 iterations of a 4x4 block: k=2 entropies
//    (4 windows) + k=4 sum/entropy in registers; 64x64 k=4 sums -> smem.
//  - Smem pyramid for k=8..256.
//  - Branch-free plogp via fmaxf (removes FSETP/SEL pred chains).
//  - __ldcs streaming loads (read-once data, evict-first).
//  - Fused finalize via atomic arrival counter; last CTA reduces 512x8
//    partials in fixed order (deterministic) and resets the counter.

#define NLEVELS 8
#define TILES_PER_IMG 16
#define NBATCH 32
#define NBLOCKS (NBATCH * TILES_PER_IMG)
#define NTHREADS 256

// pyramid: 64^2 + 32^2 + 16^2 + 8^2 + 4^2 + 2^2 + 1 = 5461 floats (21844 B)
#define SMEM_FLOATS 5461

__device__ float g_partials[NBLOCKS * NLEVELS];
__device__ int   g_count = 0;

__device__ __forceinline__ float plogp(float p) {
    // p * log2(p), 0 at p == 0 (matches ref: where(p>0,p,1) -> ps*log2(ps))
    return p * __log2f(fmaxf(p, 1.17549435e-38f));
}
__device__ __forceinline__ float ent(float s, float inv_n) {
    const float p = s * inv_n;
    return plogp(p) + plogp(1.f - p);
}

__global__ void __launch_bounds__(NTHREADS, 4)
slice_windows_fused(const float* __restrict__ x, float* __restrict__ out)
{
    __shared__ float sm[SMEM_FLOATS];
    __shared__ bool  is_last;

    const int tid  = threadIdx.x;
    const int bid  = blockIdx.x;
    const int b    = bid >> 4;
    const int tile = bid & 15;
    const int row0 = (tile >> 2) * 256;
    const int col0 = (tile & 3) * 256;
    const float* __restrict__ img = x + (size_t)b * 1024 * 1024;

    float eacc[NLEVELS];
#pragma unroll
    for (int l = 0; l < NLEVELS; l++) eacc[l] = 0.f;

    // ---- Gmem pass: k=2 and k=4 in registers; store 64x64 k=4 sums to smem.
    {
        const int c4 = tid & 63;          // 4-col group: 0..63
        const int r  = tid >> 6;          // 0..3
        const float* base = img + (size_t)row0 * 1024 + col0 + c4 * 4;
#pragma unroll
        for (int it = 0; it < 16; ++it) {
            const int orow = it * 4 + r;                // k=4 output row 0..63
            const float* p = base + (size_t)orow * 4096;
            const float4 a0 = __ldcs((const float4*)(p));
            const float4 a1 = __ldcs((const float4*)(p + 1024));
            const float4 a2 = __ldcs((const float4*)(p + 2048));
            const float4 a3 = __ldcs((const float4*)(p + 3072));
            const float s00 = (a0.x + a0.y) + (a1.x + a1.y);
            const float s01 = (a0.z + a0.w) + (a1.z + a1.w);
            const float s10 = (a2.x + a2.y) + (a3.x + a3.y);
            const float s11 = (a2.z + a2.w) + (a3.z + a3.w);
            eacc[0] -= ent(s00, 0.25f) + ent(s01, 0.25f)
                     + ent(s10, 0.25f) + ent(s11, 0.25f);
            const float S = (s00 + s01) + (s10 + s11);
            eacc[1] -= ent(S, 0.0625f);
            sm[orow * 64 + c4] = S;
        }
    }
    __syncthreads();

    // ---- Pyramid in smem: levels l=2..7 (k=8..256), 64x64 -> 1x1.
    int in_off = 0, in_dim = 64, out_off = 4096;
#pragma unroll
    for (int l = 2; l < NLEVELS; l++) {
        const int out_dim = in_dim >> 1;
        const int nout = out_dim * out_dim;
        const float inv_n = 1.0f / (float)(1 << (2 * (l + 1)));  // 1/k^2
        for (int i = tid; i < nout; i += NTHREADS) {
            const int oy = i / out_dim;
            const int ox = i - oy * out_dim;
            const float* rp0 = sm + in_off + (2 * oy) * in_dim + 2 * ox;
            const float* rp1 = rp0 + in_dim;
            const float s = (rp0[0] + rp0[1]) + (rp1[0] + rp1[1]);
            eacc[l] -= ent(s, inv_n);
            sm[out_off + i] = s;
        }
        __syncthreads();
        in_off = out_off;
        in_dim = out_dim;
        out_off += nout;
    }
    // Region sm[0..4095] is dead now -> reuse for the block reduction.

    // ---- Block-reduce the 8 per-thread entropy accumulators (8 warps).
    const int lane = tid & 31;
    const int warp = tid >> 5;
#pragma unroll
    for (int l = 0; l < NLEVELS; l++) {
        float v = eacc[l];
#pragma unroll
        for (int o = 16; o > 0; o >>= 1)
            v += __shfl_down_sync(0xffffffffu, v, o);
        if (lane == 0) sm[warp * NLEVELS + l] = v;
    }
    __syncthreads();
    if (tid < NLEVELS) {
        float s = 0.f;
#pragma unroll
        for (int w = 0; w < 8; w++) s += sm[w * NLEVELS + tid];
        g_partials[bid * NLEVELS + tid] = s;
    }

    // ---- Fused finalize: last-arriving CTA reduces all partials.
    __threadfence();
    if (tid == 0) {
        const int prev = atomicAdd(&g_count, 1);
        is_last = (prev == NBLOCKS - 1);
    }
    __syncthreads();
    if (is_last) {
        // 256 threads == NBATCH*NLEVELS outputs, one each.
        const int bb = tid >> 3;
        const int l  = tid & 7;
        float s = 0.f;
#pragma unroll
        for (int t = 0; t < TILES_PER_IMG; t++)
            s += __ldcg(&g_partials[(bb * TILES_PER_IMG + t) * NLEVELS + l]);
        const int d = 1024 >> (l + 1);   // windows per side, k = 2^(l+1)
        out[bb * NLEVELS + l] = s / (float)(d * d);
        if (tid == 0) g_count = 0;       // reset for graph replay
    }
}

extern "C" void kernel_launch(void* const* d_in, const int* in_sizes, int n_in,
                              void* d_out, int out_size)
{
    (void)in_sizes; (void)n_in; (void)out_size;
    const float* x = (const float*)d_in[0];
    float* out = (float*)d_out;
    slice_windows_fused<<<NBLOCKS, NTHREADS>>>(x, out);
}